// round 4
// baseline (speedup 1.0000x reference)
#include <cuda_runtime.h>
#include <math.h>

#define SEQ_L     200
#define NTHREADS  512
#define NWARP     (NTHREADS / 32)
#define EPS2      (1e-8f * 1e-8f)

// Staged-row layout: stride 102 floats per row (51 float2; 51 odd => pair-index
// stride 3 mod 16 => conflict-free LDS.64 across consecutive rows).
#define SV_STRIDE   102
#define SV_WORDS    (SEQ_L * SV_STRIDE)        // 20400 floats
#define SUW_OFF     SV_WORDS                   // 50 x float4 (u/w interleaved) = 200 floats
#define SRED_OFF    (SV_WORDS + 200)
#define SMEM_FLOATS (SRED_OFF + 4 * NWARP)
#define SMEM_BYTES  (SMEM_FLOATS * 4)          // ~82.7 KB

__global__ __launch_bounds__(NTHREADS, 1)
void binclf_kernel(const int*   __restrict__ word_idxs,   // [B, 200]
                   const float* __restrict__ emb_table,   // [100000, 100]
                   const float* __restrict__ weights,     // [100, 1]
                   const float* __restrict__ attend_u,    // [2, 50] (=100 linear)
                   float*       __restrict__ out)         // [B]
{
    extern __shared__ float sm[];
    float*  sv   = sm;
    float4* suw  = (float4*)(sm + SUW_OFF);
    float*  sred = sm + SRED_OFF;

    const int b    = blockIdx.x;
    const int t    = threadIdx.x;
    const int lane = t & 31;
    const int warp = t >> 5;

    // Stage u/w interleaved: suw[p] = (u[2p], w[2p], u[2p+1], w[2p+1]).
    // Element ordering e = c*50 + m matches the reference reshape.
    if (t < 100) {
        float* dst = (float*)suw;
        const int base = (t >> 1) * 4 + (t & 1) * 2;
        dst[base + 0] = attend_u[t];
        dst[base + 1] = weights[t];
    }

    // Stage the 200 gathered rows as float2 (coalesced LDG, conflict-free STS).
    const int* idxp = word_idxs + (size_t)b * SEQ_L;
    for (int j = t; j < SEQ_L * 50; j += NTHREADS) {
        const int r = j / 50;
        const int p = j - r * 50;
        const int idx = __ldg(idxp + r);
        float2 v = __ldg((const float2*)(emb_table + (size_t)idx * 100) + p);
        *(float2*)(sv + r * SV_STRIDE + 2 * p) = v;
    }
    __syncthreads();

    // Every warp redundantly computes 1/max(||u_c||, eps)  (once per block, cheap)
    float su0 = 0.f, su1 = 0.f;
    if (lane < 25) {
        float4 a = suw[lane];
        float4 c = suw[25 + lane];
        su0 = a.x * a.x + a.z * a.z;
        su1 = c.x * c.x + c.z * c.z;
    }
    #pragma unroll
    for (int o = 16; o > 0; o >>= 1) {
        su0 += __shfl_xor_sync(0xffffffffu, su0, o);
        su1 += __shfl_xor_sync(0xffffffffu, su1, o);
    }
    const float uinv0 = rsqrtf(fmaxf(su0, EPS2));
    const float uinv1 = rsqrtf(fmaxf(su1, EPS2));

    // One (l, chunk) task per thread: fully serial dot products, no shuffles.
    float p0 = 0.f, p1 = 0.f, A0 = 0.f, A1 = 0.f;
    if (t < 2 * SEQ_L) {
        const int c = (t >= SEQ_L) ? 1 : 0;
        const int l = t - c * SEQ_L;
        const float2* vp = (const float2*)(sv + l * SV_STRIDE + 50 * c);
        const float4* up = suw + 25 * c;

        float sa = 0.f, sb = 0.f, da = 0.f, db = 0.f, wa = 0.f, wb = 0.f;
        #pragma unroll
        for (int j = 0; j < 25; j++) {
            const float2 v  = vp[j];
            const float4 u4 = up[j];   // uniform per warp -> broadcast
            sa = fmaf(v.x, v.x,  sa);  sb = fmaf(v.y, v.y,  sb);
            da = fmaf(v.x, u4.x, da);  db = fmaf(v.y, u4.z, db);
            wa = fmaf(v.x, u4.y, wa);  wb = fmaf(v.y, u4.w, wb);
        }
        const float s  = sa + sb;
        const float d  = da + db;
        const float wd = wa + wb;
        const float ui = c ? uinv1 : uinv0;
        const float a  = __expf(d * rsqrtf(fmaxf(s, EPS2)) * ui);
        if (c) { p1 = a * wd; A1 = a; }
        else   { p0 = a * wd; A0 = a; }
    }

    // Single block-level reduction of 4 scalars (once per block).
    #pragma unroll
    for (int o = 16; o > 0; o >>= 1) {
        p0 += __shfl_xor_sync(0xffffffffu, p0, o);
        p1 += __shfl_xor_sync(0xffffffffu, p1, o);
        A0 += __shfl_xor_sync(0xffffffffu, A0, o);
        A1 += __shfl_xor_sync(0xffffffffu, A1, o);
    }
    if (lane == 0) {
        sred[warp * 4 + 0] = p0;
        sred[warp * 4 + 1] = p1;
        sred[warp * 4 + 2] = A0;
        sred[warp * 4 + 3] = A1;
    }
    __syncthreads();

    if (t == 0) {
        float P0 = 0.f, P1 = 0.f, S0 = 0.f, S1 = 0.f;
        #pragma unroll
        for (int w = 0; w < NWARP; w++) {
            P0 += sred[w * 4 + 0];
            P1 += sred[w * 4 + 1];
            S0 += sred[w * 4 + 2];
            S1 += sred[w * 4 + 3];
        }
        out[b] = P0 / S0 + P1 / S1;
    }
}

extern "C" void kernel_launch(void* const* d_in, const int* in_sizes, int n_in,
                              void* d_out, int out_size)
{
    const int*   word_idxs = (const int*)  d_in[0];  // [B, 200] int32
    const float* emb_table = (const float*)d_in[1];  // [100000, 100] f32
    const float* weights   = (const float*)d_in[2];  // [100, 1] f32
    const float* attend_u  = (const float*)d_in[3];  // [2, 50] f32
    float*       out       = (float*)d_out;          // [B] f32

    const int B = in_sizes[0] / SEQ_L;

    cudaFuncSetAttribute(binclf_kernel,
                         cudaFuncAttributeMaxDynamicSharedMemorySize, SMEM_BYTES);
    binclf_kernel<<<B, NTHREADS, SMEM_BYTES>>>(word_idxs, emb_table, weights,
                                               attend_u, out);
}

// round 5
// speedup vs baseline: 1.8310x; 1.8310x over previous
#include <cuda_runtime.h>
#include <math.h>
#include <stdint.h>

#define SEQ_L          200
#define WORDS_PER_BLK  50
#define BLKS_PER_B     4
#define NTHREADS       128
#define EPS2           (1e-8f * 1e-8f)

// Row stage stride: 102 floats = 51 float2. 51 mod 16 = 3 (odd) => lane l
// reads float2-index 51*l + const => bank 3*l mod 16 => conflict-free LDS.64.
#define SV_STRIDE      102
#define SV_FLOATS      (WORDS_PER_BLK * SV_STRIDE)   // 5100
#define SUW_OFF        SV_FLOATS                     // 50 x float4 = 200 floats
#define SRED_OFF       (SUW_OFF + 200)
#define SMEM_FLOATS    (SRED_OFF + 8)
#define SMEM_BYTES     (SMEM_FLOATS * 4)             // 21232 B

#define MAX_B 8192
__device__ float g_part[MAX_B * BLKS_PER_B * 4];

typedef unsigned long long u64_t;

__device__ __forceinline__ uint32_t smem_u32(const void* p) {
    return (uint32_t)__cvta_generic_to_shared(p);
}
__device__ __forceinline__ u64_t lds64(uint32_t a) {
    u64_t v; asm volatile("ld.shared.b64 %0, [%1];" : "=l"(v) : "r"(a)); return v;
}
__device__ __forceinline__ void lds_v2_64(uint32_t a, u64_t& x, u64_t& y) {
    asm volatile("ld.shared.v2.b64 {%0,%1}, [%2];" : "=l"(x), "=l"(y) : "r"(a));
}
__device__ __forceinline__ u64_t ffma2(u64_t a, u64_t b, u64_t c) {
    u64_t d; asm("fma.rn.f32x2 %0, %1, %2, %3;" : "=l"(d) : "l"(a), "l"(b), "l"(c));
    return d;
}
__device__ __forceinline__ float lo_f(u64_t v) { return __uint_as_float((uint32_t)v); }
__device__ __forceinline__ float hi_f(u64_t v) { return __uint_as_float((uint32_t)(v >> 32)); }

// Block = (b, quarter): stages 50 gathered rows into smem, then one thread per
// (word, chunk) task computes s=||ch||^2, d=ch.u, wd=ch.w serially with packed
// f32x2 FMAs (no per-word cross-lane reductions). 4 scalars per block out.
__global__ __launch_bounds__(NTHREADS, 8)
void binclf_main(const int*   __restrict__ word_idxs,   // [B, 200]
                 const float* __restrict__ emb_table,   // [100000, 100]
                 const float* __restrict__ weights,     // [100]
                 const float* __restrict__ attend_u)    // [100] (chunk-major)
{
    extern __shared__ float sm[];
    float*  sv   = sm;
    float4* suw  = (float4*)(sm + SUW_OFF);
    float*  sred = sm + SRED_OFF;

    const int blk  = blockIdx.x;
    const int b    = blk >> 2;
    const int l0   = (blk & 3) * WORDS_PER_BLK;
    const int t    = threadIdx.x;
    const int lane = t & 31;
    const int warp = t >> 5;

    // Stage u/w as (u[2j], u[2j+1], w[2j], w[2j+1]) per (chunk, j).
    if (t < 50) {
        const int c = t / 25, j = t - c * 25;
        const int e = c * 50 + 2 * j;
        suw[c * 25 + j] = make_float4(attend_u[e], attend_u[e + 1],
                                      weights[e],  weights[e + 1]);
    }

    // Stage 50 gathered rows (coalesced float2 loads, conflict-free STS).
    const int* idxp = word_idxs + (size_t)b * SEQ_L + l0;
    for (int j = t; j < WORDS_PER_BLK * 50; j += NTHREADS) {
        const int r = j / 50;
        const int p = j - r * 50;
        const int idx = __ldg(idxp + r);
        float2 v = __ldg((const float2*)(emb_table + (size_t)idx * 100) + p);
        *(float2*)(sv + r * SV_STRIDE + 2 * p) = v;
    }
    __syncthreads();

    // Warp-uniform chunk: warps 0,1 -> chunk 0; warps 2,3 -> chunk 1.
    const int c = warp >> 1;

    // Per-warp redundant 1/max(||u_c||, eps).
    float uu = 0.f;
    if (lane < 25) {
        float4 q = suw[c * 25 + lane];
        uu = q.x * q.x + q.y * q.y;
    }
    #pragma unroll
    for (int o = 16; o > 0; o >>= 1)
        uu += __shfl_xor_sync(0xffffffffu, uu, o);
    const float uinv = rsqrtf(fmaxf(uu, EPS2));

    // Task map: c0 -> t in [0,50); c1 -> t in [64,114).
    const bool active = c ? (t >= 64 && t < 64 + WORDS_PER_BLK)
                          : (t < WORDS_PER_BLK);
    float p = 0.f, A = 0.f;
    if (active) {
        const int l = c ? (t - 64) : t;
        const uint32_t vaddr  = smem_u32(sv + l * SV_STRIDE + 50 * c);
        const uint32_t uwaddr = smem_u32(suw + 25 * c);

        u64_t ss = 0ull, dd = 0ull, ww = 0ull;   // packed (0.f, 0.f)
        #pragma unroll
        for (int j = 0; j < 25; j++) {
            u64_t v = lds64(vaddr + 8 * j);
            u64_t u2, w2;
            lds_v2_64(uwaddr + 16 * j, u2, w2);
            ss = ffma2(v, v,  ss);
            dd = ffma2(v, u2, dd);
            ww = ffma2(v, w2, ww);
        }
        const float s  = lo_f(ss) + hi_f(ss);
        const float d  = lo_f(dd) + hi_f(dd);
        const float wd = lo_f(ww) + hi_f(ww);
        const float a  = __expf(d * rsqrtf(fmaxf(s, EPS2)) * uinv);
        p = a * wd;
        A = a;
    }

    // One tiny reduction per block (uniform-c warps).
    #pragma unroll
    for (int o = 16; o > 0; o >>= 1) {
        p += __shfl_xor_sync(0xffffffffu, p, o);
        A += __shfl_xor_sync(0xffffffffu, A, o);
    }
    if (lane == 0) {
        sred[warp * 2 + 0] = p;
        sred[warp * 2 + 1] = A;
    }
    __syncthreads();

    if (t == 0) {
        float* o = g_part + (size_t)blk * 4;
        o[0] = sred[0] + sred[2];   // p0
        o[1] = sred[1] + sred[3];   // A0
        o[2] = sred[4] + sred[6];   // p1
        o[3] = sred[5] + sred[7];   // A1
    }
}

__global__ void binclf_fin(float* __restrict__ out, int B)
{
    const int b = blockIdx.x * blockDim.x + threadIdx.x;
    if (b >= B) return;
    const float* g = g_part + (size_t)b * BLKS_PER_B * 4;
    float P0 = 0.f, A0 = 0.f, P1 = 0.f, A1 = 0.f;
    #pragma unroll
    for (int q = 0; q < BLKS_PER_B; q++) {
        P0 += g[q * 4 + 0];
        A0 += g[q * 4 + 1];
        P1 += g[q * 4 + 2];
        A1 += g[q * 4 + 3];
    }
    out[b] = P0 / A0 + P1 / A1;
}

extern "C" void kernel_launch(void* const* d_in, const int* in_sizes, int n_in,
                              void* d_out, int out_size)
{
    const int*   word_idxs = (const int*)  d_in[0];  // [B, 200] int32
    const float* emb_table = (const float*)d_in[1];  // [100000, 100] f32
    const float* weights   = (const float*)d_in[2];  // [100, 1] f32
    const float* attend_u  = (const float*)d_in[3];  // [2, 50] f32
    float*       out       = (float*)d_out;          // [B] f32

    const int B = in_sizes[0] / SEQ_L;

    binclf_main<<<B * BLKS_PER_B, NTHREADS, SMEM_BYTES>>>(word_idxs, emb_table,
                                                          weights, attend_u);
    binclf_fin<<<(B + 255) / 256, 256>>>(out, B);
}

// round 6
// speedup vs baseline: 2.8354x; 1.5486x over previous
#include <cuda_runtime.h>
#include <stdint.h>
#include <math.h>

#define SEQ_L        200
#define ROWS_PER_BLK 100
#define BLKS_PER_B   2
#define NT           256
#define EPS2         (1e-8f * 1e-8f)
#define NF4          (ROWS_PER_BLK * 25)   // 2500 staged float4 per block

#define MAX_B 8192
__device__ float4 g_part[MAX_B * BLKS_PER_B];

typedef unsigned long long u64_t;

__device__ __forceinline__ u64_t pk(float x, float y) {
    u64_t r;
    asm("mov.b64 %0, {%1, %2};" : "=l"(r)
        : "r"(__float_as_uint(x)), "r"(__float_as_uint(y)));
    return r;
}
__device__ __forceinline__ u64_t ffma2(u64_t a, u64_t b, u64_t c) {
    u64_t d; asm("fma.rn.f32x2 %0, %1, %2, %3;" : "=l"(d) : "l"(a), "l"(b), "l"(c));
    return d;
}
__device__ __forceinline__ float psum(u64_t v) {
    return __uint_as_float((uint32_t)v) + __uint_as_float((uint32_t)(v >> 32));
}

// Block = (b, half). Stage 100 gathered rows compactly (25 f4/row), then one
// thread per (row, chunk) computes s=||ch||^2, d=ch.u, wd=ch.w serially.
__global__ __launch_bounds__(NT, 4)
void binclf_main(const int*   __restrict__ word_idxs,   // [B, 200]
                 const float* __restrict__ emb_table,   // [100000, 100]
                 const float* __restrict__ weights,     // [100]
                 const float* __restrict__ attend_u)    // [100] chunk-major
{
    __shared__ float4 sv4[NF4];     // 40000 B
    __shared__ float4 su4[25];
    __shared__ float4 sw4[25];
    __shared__ float  sred[16];

    const int blk  = blockIdx.x;
    const int b    = blk >> 1;
    const int l0   = (blk & 1) * ROWS_PER_BLK;
    const int t    = threadIdx.x;
    const int lane = t & 31;
    const int w    = t >> 5;

    // Stage u / w (100 contiguous floats each, chunk-major ordering matches ref).
    if (t < 25)                su4[t]      = ((const float4*)attend_u)[t];
    else if (t >= 32 && t < 57) sw4[t - 32] = ((const float4*)weights)[t - 32];

    // ---- Stage 2500 float4: linear STS, row-contiguous LDG, batched MLP ----
    const int* idxp = word_idxs + (size_t)b * SEQ_L + l0;
    #pragma unroll
    for (int kb = 0; kb < 10; kb += 5) {
        const float4* ga[5];
        int jj[5];
        #pragma unroll
        for (int q = 0; q < 5; q++) {
            const int j = t + (kb + q) * NT;
            jj[q] = j;
            if (j < NF4) {
                const int row  = j / 25;          // constant divisor -> mul/shift
                const int slot = j - row * 25;
                const int idx  = __ldg(idxp + row);
                ga[q] = (const float4*)(emb_table + (size_t)idx * 100) + slot;
            }
        }
        #pragma unroll
        for (int q = 0; q < 5; q++)
            if (jj[q] < NF4) sv4[jj[q]] = __ldg(ga[q]);
    }
    __syncthreads();

    // Warp-uniform chunk: warps 0-3 -> chunk 0 (rows 0-99), warps 4-7 -> chunk 1.
    const int c = w >> 2;

    // Per-warp 1/max(||u_c||, eps): chunk c covers f4 [13c, 13c+12) + half of f4 12.
    float uu = 0.f;
    if (lane < 12) {
        const float4 q = su4[13 * c + lane];
        uu = q.x * q.x + q.y * q.y + q.z * q.z + q.w * q.w;
    } else if (lane == 12) {
        const float4 q = su4[12];
        uu = c ? (q.z * q.z + q.w * q.w) : (q.x * q.x + q.y * q.y);
    }
    #pragma unroll
    for (int o = 16; o > 0; o >>= 1)
        uu += __shfl_xor_sync(0xffffffffu, uu, o);
    const float uinv = rsqrtf(fmaxf(uu, EPS2));

    // ---- One (row, chunk) task per thread: serial dots, conflict-free LDS.128 ----
    float p = 0.f, A = 0.f;
    if (lane < 25) {
        const int row   = (w & 3) * 25 + lane;            // 0..99
        const int vbase = row * 25 + 13 * c;
        const int ubase = 13 * c;

        u64_t s0 = 0ull, s1 = 0ull, d0 = 0ull, d1 = 0ull, w0 = 0ull, w1 = 0ull;
        #pragma unroll
        for (int j = 0; j < 12; j++) {
            const float4 v = sv4[vbase + j];
            const float4 u = su4[ubase + j];              // broadcast
            const float4 q = sw4[ubase + j];              // broadcast
            const u64_t vlo = pk(v.x, v.y), vhi = pk(v.z, v.w);
            s0 = ffma2(vlo, vlo, s0);            s1 = ffma2(vhi, vhi, s1);
            d0 = ffma2(vlo, pk(u.x, u.y), d0);   d1 = ffma2(vhi, pk(u.z, u.w), d1);
            w0 = ffma2(vlo, pk(q.x, q.y), w0);   w1 = ffma2(vhi, pk(q.z, q.w), w1);
        }
        float s  = psum(s0) + psum(s1);
        float d  = psum(d0) + psum(d1);
        float wd = psum(w0) + psum(w1);

        // Boundary float4 #12 (floats 48-51): x,y -> chunk 0; z,w -> chunk 1.
        const float4 vb = sv4[row * 25 + 12];
        const float4 ub = su4[12];
        const float4 qb = sw4[12];
        const float ex = c ? vb.z : vb.x,  ey = c ? vb.w : vb.y;
        const float ux = c ? ub.z : ub.x,  uy = c ? ub.w : ub.y;
        const float wx = c ? qb.z : qb.x,  wy = c ? qb.w : qb.y;
        s  = fmaf(ex, ex, fmaf(ey, ey, s));
        d  = fmaf(ex, ux, fmaf(ey, uy, d));
        wd = fmaf(ex, wx, fmaf(ey, wy, wd));

        const float a = __expf(d * rsqrtf(fmaxf(s, EPS2)) * uinv);
        p = a * wd;
        A = a;
    }

    // Block reduction: butterfly within warp, tiny cross-warp combine.
    #pragma unroll
    for (int o = 16; o > 0; o >>= 1) {
        p += __shfl_xor_sync(0xffffffffu, p, o);
        A += __shfl_xor_sync(0xffffffffu, A, o);
    }
    if (lane == 0) { sred[w * 2] = p; sred[w * 2 + 1] = A; }
    __syncthreads();

    if (t == 0) {
        float p0 = 0.f, A0 = 0.f, p1 = 0.f, A1 = 0.f;
        #pragma unroll
        for (int k = 0; k < 4; k++) {
            p0 += sred[2 * k];          A0 += sred[2 * k + 1];
            p1 += sred[8 + 2 * k];      A1 += sred[8 + 2 * k + 1];
        }
        g_part[blk] = make_float4(p0, A0, p1, A1);
    }
}

__global__ void binclf_fin(float* __restrict__ out, int B)
{
    const int b = blockIdx.x * blockDim.x + threadIdx.x;
    if (b >= B) return;
    const float4 x = g_part[2 * b];
    const float4 y = g_part[2 * b + 1];
    out[b] = (x.x + y.x) / (x.y + y.y) + (x.z + y.z) / (x.w + y.w);
}

extern "C" void kernel_launch(void* const* d_in, const int* in_sizes, int n_in,
                              void* d_out, int out_size)
{
    const int*   word_idxs = (const int*)  d_in[0];  // [B, 200] int32
    const float* emb_table = (const float*)d_in[1];  // [100000, 100] f32
    const float* weights   = (const float*)d_in[2];  // [100, 1] f32
    const float* attend_u  = (const float*)d_in[3];  // [2, 50] f32
    float*       out       = (float*)d_out;          // [B] f32

    const int B = in_sizes[0] / SEQ_L;

    binclf_main<<<B * BLKS_PER_B, NT>>>(word_idxs, emb_table, weights, attend_u);
    binclf_fin<<<(B + 255) / 256, 256>>>(out, B);
}